// round 5
// baseline (speedup 1.0000x reference)
#include <cuda_runtime.h>

// ---------------------------------------------------------------------------
// GRU encoder-decoder, persistent per-CTA recurrence, f32x2-packed compute.
// R3: NT=512 (16 warps/SM, 4/SMSP) for latency hiding; thread tile = 2 rows x
// 2 units (units packed in f32x2 lanes). Weight SMEM layout interleaves r,z
// pairs so one LDS.128 feeds two gates; n pairs separate (LDS.64).
// Double-buffered hidden state -> 2 syncs/enc step.
// ---------------------------------------------------------------------------

typedef unsigned long long u64;

#define Hh     64
#define G3     192
#define ROWS   32
#define NT     512
#define TSEQ   256
#define NINP   6

// SMEM float offsets
#define OFF_WX0RZ  0        // [8][128]
#define OFF_WX0N   1024     // [8][64]
#define OFF_WH0RZ  1536     // [64][128]
#define OFF_WH0N   9728     // [64][64]
#define OFF_WX1RZ  13824    // [64][128]
#define OFF_WX1N   22016    // [64][64]
#define OFF_WH1RZ  26112    // [64][128]
#define OFF_WH1N   34304    // [64][64]
#define OFF_HS0    38400    // [2][64][32]
#define OFF_HS1    42496    // [2][64][32]
#define OFF_XS     46592    // [2][8][32]
#define OFF_OW     47104    // [64]
#define OFF_OB     47168    // [1]
#define SMEM_FLOATS 47172   // 188,688 bytes

__device__ __forceinline__ u64 pk2(float lo, float hi) {
    u64 r; asm("mov.b64 %0, {%1,%2};" : "=l"(r) : "f"(lo), "f"(hi)); return r;
}
__device__ __forceinline__ u64 dup2(float v) { return pk2(v, v); }
__device__ __forceinline__ float2 up2(u64 v) {
    float2 r; asm("mov.b64 {%0,%1}, %2;" : "=f"(r.x), "=f"(r.y) : "l"(v)); return r;
}
#define FFMA2(acc, a, b) \
    asm("fma.rn.f32x2 %0, %1, %2, %0;" : "+l"(acc) : "l"(a), "l"(b))

__device__ __forceinline__ float sigf(float x) {
    return 1.0f / (1.0f + __expf(-x));
}
__device__ __forceinline__ float tanhfast(float x) {
    float e = __expf(-2.0f * fabsf(x));
    float t = (1.0f - e) / (1.0f + e);
    return copysignf(t, x);
}

// Split-transpose W[192][K] (row-major) into:
//   rz[k*128 + ut*4 + gate*2 + lane]  (gates r,z)
//   n [k*64  + ut*2 + lane]           (gate n)
__device__ __forceinline__ void load_w_split(float* dstRZ, float* dstN,
                                             const float* __restrict__ src,
                                             int K, int tid) {
    for (int idx = tid; idx < G3 * K; idx += NT) {
        int g = idx / K;
        int k = idx - g * K;
        int gate = g >> 6;          // 0=r,1=z,2=n
        int j    = g & 63;
        int ut   = j >> 1;
        int lane = j & 1;
        float v = src[idx];
        if (gate < 2) dstRZ[k * 128 + ut * 4 + gate * 2 + lane] = v;
        else          dstN [k * 64  + ut * 2 + lane]            = v;
    }
}

// GRU cell for this thread's [2 units (packed f32x2) x 2 rows] tile.
// xsrc/hsrc k-major [k][ROWS]; weights in split rz/n layout.
template<int KIN>
__device__ __forceinline__ void gru_tile2(
    const float* __restrict__ Wxrz, const float* __restrict__ Wxn,
    const float* __restrict__ Whrz, const float* __restrict__ Whn,
    const float* __restrict__ xsrc, const float* __restrict__ hsrc,
    float* __restrict__ hdst,
    u64 br2, u64 bz2, u64 bi2, u64 bh2,
    int ut, int r0)
{
    u64 ar[2], az[2], ai[2], ah[2];
    ar[0] = br2; ar[1] = br2;
    az[0] = bz2; az[1] = bz2;
    ai[0] = bi2; ai[1] = bi2;
    ah[0] = bh2; ah[1] = bh2;

    const float* wxrz = Wxrz + ut * 4;
    const float* wxn  = Wxn  + ut * 2;
#pragma unroll
    for (int k = 0; k < KIN; k++) {
        float2 xv = *(const float2*)(xsrc + k * ROWS + r0);
        ulonglong2 wv = *(const ulonglong2*)(wxrz + k * 128);
        u64 wn = *(const u64*)(wxn + k * 64);
        u64 x0 = dup2(xv.x), x1 = dup2(xv.y);
        FFMA2(ar[0], wv.x, x0); FFMA2(ar[1], wv.x, x1);
        FFMA2(az[0], wv.y, x0); FFMA2(az[1], wv.y, x1);
        FFMA2(ai[0], wn,   x0); FFMA2(ai[1], wn,   x1);
    }

    const float* whrz = Whrz + ut * 4;
    const float* whn  = Whn  + ut * 2;
#pragma unroll 8
    for (int k = 0; k < Hh; k++) {
        float2 hv = *(const float2*)(hsrc + k * ROWS + r0);
        ulonglong2 wv = *(const ulonglong2*)(whrz + k * 128);
        u64 wn = *(const u64*)(whn + k * 64);
        u64 h0 = dup2(hv.x), h1 = dup2(hv.y);
        FFMA2(ar[0], wv.x, h0); FFMA2(ar[1], wv.x, h1);
        FFMA2(az[0], wv.y, h0); FFMA2(az[1], wv.y, h1);
        FFMA2(ah[0], wn,   h0); FFMA2(ah[1], wn,   h1);
    }

    // epilogue: r,z sigmoid; n = tanh(in + r*hn); h' = n + z*(h_old - n)
    const int j0 = ut * 2;
    float2 ho0 = *(const float2*)(hsrc + j0 * ROWS + r0);        // unit0, rows 0..1
    float2 ho1 = *(const float2*)(hsrc + (j0 + 1) * ROWS + r0);  // unit1
    float o0[2], o1[2];
    float hou0[2] = {ho0.x, ho0.y}, hou1[2] = {ho1.x, ho1.y};
#pragma unroll
    for (int rr = 0; rr < 2; rr++) {
        float2 arv = up2(ar[rr]), azv = up2(az[rr]);
        float2 aiv = up2(ai[rr]), ahv = up2(ah[rr]);
        {
            float r = sigf(arv.x), z = sigf(azv.x);
            float n = tanhfast(fmaf(r, ahv.x, aiv.x));
            o0[rr] = fmaf(z, hou0[rr] - n, n);
        }
        {
            float r = sigf(arv.y), z = sigf(azv.y);
            float n = tanhfast(fmaf(r, ahv.y, aiv.y));
            o1[rr] = fmaf(z, hou1[rr] - n, n);
        }
    }
    *(float2*)(hdst + j0 * ROWS + r0)       = make_float2(o0[0], o0[1]);
    *(float2*)(hdst + (j0 + 1) * ROWS + r0) = make_float2(o1[0], o1[1]);
}

extern __shared__ float sm[];

__global__ __launch_bounds__(NT, 1)
void gru_kernel(
    const float* __restrict__ x,
    const float* __restrict__ eWih0, const float* __restrict__ eWhh0,
    const float* __restrict__ ebih0, const float* __restrict__ ebhh0,
    const float* __restrict__ eWih1, const float* __restrict__ eWhh1,
    const float* __restrict__ ebih1, const float* __restrict__ ebhh1,
    const float* __restrict__ dWih0, const float* __restrict__ dWhh0,
    const float* __restrict__ dbih0, const float* __restrict__ dbhh0,
    const float* __restrict__ dWih1, const float* __restrict__ dWhh1,
    const float* __restrict__ dbih1, const float* __restrict__ dbhh1,
    const float* __restrict__ outW, const float* __restrict__ outb,
    float* __restrict__ out, int Bn, int TL)
{
    const int tid = threadIdx.x;
    const int b0  = blockIdx.x * ROWS;

    float* Wx0rz = sm + OFF_WX0RZ;  float* Wx0n = sm + OFF_WX0N;
    float* Wh0rz = sm + OFF_WH0RZ;  float* Wh0n = sm + OFF_WH0N;
    float* Wx1rz = sm + OFF_WX1RZ;  float* Wx1n = sm + OFF_WX1N;
    float* Wh1rz = sm + OFF_WH1RZ;  float* Wh1n = sm + OFF_WH1N;
    float* hs0 = sm + OFF_HS0;
    float* hs1 = sm + OFF_HS1;
    float* xs  = sm + OFF_XS;
    float* sOW = sm + OFF_OW;
    float* sOB = sm + OFF_OB;

    const int rt = tid & 15;         // row tile (2 rows)
    const int ut = tid >> 4;         // unit tile (2 units)
    const int r0 = rt * 2;
    const int j0 = ut * 2;

    // ---- stage encoder weights ----
    load_w_split(Wx0rz, Wx0n, eWih0, NINP, tid);
    load_w_split(Wh0rz, Wh0n, eWhh0, Hh, tid);
    load_w_split(Wx1rz, Wx1n, eWih1, Hh, tid);
    load_w_split(Wh1rz, Wh1n, eWhh1, Hh, tid);
    for (int i = tid; i < Hh * ROWS; i += NT) {
        hs0[i] = 0.0f; hs0[2048 + i] = 0.0f;
        hs1[i] = 0.0f; hs1[2048 + i] = 0.0f;
    }

    // ---- encoder bias pairs in registers ----
    u64 b0r, b0z, b0i, b0h, b1r, b1z, b1i, b1h;
    {
        float2 a, b;
        a = *(const float2*)(ebih0 + j0);        b = *(const float2*)(ebhh0 + j0);
        b0r = pk2(a.x + b.x, a.y + b.y);
        a = *(const float2*)(ebih0 + 64 + j0);   b = *(const float2*)(ebhh0 + 64 + j0);
        b0z = pk2(a.x + b.x, a.y + b.y);
        a = *(const float2*)(ebih0 + 128 + j0);  b0i = pk2(a.x, a.y);
        b = *(const float2*)(ebhh0 + 128 + j0);  b0h = pk2(b.x, b.y);
        a = *(const float2*)(ebih1 + j0);        b = *(const float2*)(ebhh1 + j0);
        b1r = pk2(a.x + b.x, a.y + b.y);
        a = *(const float2*)(ebih1 + 64 + j0);   b = *(const float2*)(ebhh1 + 64 + j0);
        b1z = pk2(a.x + b.x, a.y + b.y);
        a = *(const float2*)(ebih1 + 128 + j0);  b1i = pk2(a.x, a.y);
        b = *(const float2*)(ebhh1 + 128 + j0);  b1h = pk2(b.x, b.y);
    }

    // prestage x for t=0 into buffer 0
    const int xi = tid >> 5, xr = tid & 31;
    if (tid < NINP * ROWS) {
        float v = (b0 + xr < Bn)
            ? x[(size_t)(b0 + xr) * (TSEQ * NINP) + xi] : 0.0f;
        xs[xi * ROWS + xr] = v;
    }
    __syncthreads();

    // ---- encoder: 256 steps ----
    int cur = 0;
    for (int t = 0; t < TSEQ; t++) {
        float xreg = 0.0f;
        if (tid < NINP * ROWS && t + 1 < TSEQ && b0 + xr < Bn)
            xreg = x[(size_t)(b0 + xr) * (TSEQ * NINP) + (size_t)(t + 1) * NINP + xi];
        int nxt = cur ^ 1;
        gru_tile2<NINP>(Wx0rz, Wx0n, Wh0rz, Wh0n,
                        xs + cur * 256, hs0 + cur * 2048, hs0 + nxt * 2048,
                        b0r, b0z, b0i, b0h, ut, r0);
        if (tid < NINP * ROWS) xs[nxt * 256 + xi * ROWS + xr] = xreg;
        __syncthreads();
        gru_tile2<Hh>(Wx1rz, Wx1n, Wh1rz, Wh1n,
                      hs0 + nxt * 2048, hs1 + cur * 2048, hs1 + nxt * 2048,
                      b1r, b1z, b1i, b1h, ut, r0);
        cur = nxt;
        __syncthreads();
    }

    // ---- swap in decoder weights ----
    load_w_split(Wx0rz, Wx0n, dWih0, 1, tid);
    load_w_split(Wh0rz, Wh0n, dWhh0, Hh, tid);
    load_w_split(Wx1rz, Wx1n, dWih1, Hh, tid);
    load_w_split(Wh1rz, Wh1n, dWhh1, Hh, tid);
    if (tid < Hh) sOW[tid] = outW[tid];
    if (tid == 0) sOB[0] = outb[0];
    if (tid < ROWS) xs[tid] = 0.0f;      // prev cv = 0 (xs buffer 0, row-major k=0)
    {
        float2 a, b;
        a = *(const float2*)(dbih0 + j0);        b = *(const float2*)(dbhh0 + j0);
        b0r = pk2(a.x + b.x, a.y + b.y);
        a = *(const float2*)(dbih0 + 64 + j0);   b = *(const float2*)(dbhh0 + 64 + j0);
        b0z = pk2(a.x + b.x, a.y + b.y);
        a = *(const float2*)(dbih0 + 128 + j0);  b0i = pk2(a.x, a.y);
        b = *(const float2*)(dbhh0 + 128 + j0);  b0h = pk2(b.x, b.y);
        a = *(const float2*)(dbih1 + j0);        b = *(const float2*)(dbhh1 + j0);
        b1r = pk2(a.x + b.x, a.y + b.y);
        a = *(const float2*)(dbih1 + 64 + j0);   b = *(const float2*)(dbhh1 + 64 + j0);
        b1z = pk2(a.x + b.x, a.y + b.y);
        a = *(const float2*)(dbih1 + 128 + j0);  b1i = pk2(a.x, a.y);
        b = *(const float2*)(dbhh1 + 128 + j0);  b1h = pk2(b.x, b.y);
    }
    __syncthreads();

    // ---- decoder: TL autoregressive steps ----
    for (int s = 0; s < TL; s++) {
        int nxt = cur ^ 1;
        gru_tile2<1>(Wx0rz, Wx0n, Wh0rz, Wh0n,
                     xs, hs0 + cur * 2048, hs0 + nxt * 2048,
                     b0r, b0z, b0i, b0h, ut, r0);
        __syncthreads();
        gru_tile2<Hh>(Wx1rz, Wx1n, Wh1rz, Wh1n,
                      hs0 + nxt * 2048, hs1 + cur * 2048, hs1 + nxt * 2048,
                      b1r, b1z, b1i, b1h, ut, r0);
        __syncthreads();
        if (tid < ROWS) {
            float acc = sOB[0];
            const float* hp = hs1 + nxt * 2048 + tid;
            #pragma unroll 8
            for (int j = 0; j < Hh; j++)
                acc = fmaf(sOW[j], hp[j * ROWS], acc);
            if (b0 + tid < Bn)
                out[(size_t)(b0 + tid) * TL + s] = acc;
            xs[tid] = acc;
        }
        cur = nxt;
        __syncthreads();
    }
}

extern "C" void kernel_launch(void* const* d_in, const int* in_sizes, int n_in,
                              void* d_out, int out_size) {
    const float* x      = (const float*)d_in[0];
    const float* eWih0  = (const float*)d_in[1];
    const float* eWhh0  = (const float*)d_in[2];
    const float* ebih0  = (const float*)d_in[3];
    const float* ebhh0  = (const float*)d_in[4];
    const float* eWih1  = (const float*)d_in[5];
    const float* eWhh1  = (const float*)d_in[6];
    const float* ebih1  = (const float*)d_in[7];
    const float* ebhh1  = (const float*)d_in[8];
    const float* dWih0  = (const float*)d_in[9];
    const float* dWhh0  = (const float*)d_in[10];
    const float* dbih0  = (const float*)d_in[11];
    const float* dbhh0  = (const float*)d_in[12];
    const float* dWih1  = (const float*)d_in[13];
    const float* dWhh1  = (const float*)d_in[14];
    const float* dbih1  = (const float*)d_in[15];
    const float* dbhh1  = (const float*)d_in[16];
    const float* outW   = (const float*)d_in[17];
    const float* outb   = (const float*)d_in[18];

    int B  = in_sizes[0] / (TSEQ * NINP);
    int TL = out_size / B;                       // 180
    int grid = (B + ROWS - 1) / ROWS;            // 128
    size_t smem = SMEM_FLOATS * sizeof(float);   // ~188 KB

    cudaFuncSetAttribute(gru_kernel,
                         cudaFuncAttributeMaxDynamicSharedMemorySize,
                         (int)smem);

    gru_kernel<<<grid, NT, smem>>>(
        x, eWih0, eWhh0, ebih0, ebhh0, eWih1, eWhh1, ebih1, ebhh1,
        dWih0, dWhh0, dbih0, dbhh0, dWih1, dWhh1, dbih1, dbhh1,
        outW, outb, (float*)d_out, B, TL);
}

// round 6
// speedup vs baseline: 1.0005x; 1.0005x over previous
#include <cuda_runtime.h>

// ---------------------------------------------------------------------------
// GRU encoder-decoder, persistent per-CTA recurrence, f32x2-packed compute.
// R3: NT=512 (16 warps/SM, 4/SMSP) for latency hiding; thread tile = 2 rows x
// 2 units (units packed in f32x2 lanes). Weight SMEM layout interleaves r,z
// pairs so one LDS.128 feeds two gates; n pairs separate (LDS.64).
// Double-buffered hidden state -> 2 syncs/enc step.
// ---------------------------------------------------------------------------

typedef unsigned long long u64;

#define Hh     64
#define G3     192
#define ROWS   32
#define NT     512
#define TSEQ   256
#define NINP   6

// SMEM float offsets
#define OFF_WX0RZ  0        // [8][128]
#define OFF_WX0N   1024     // [8][64]
#define OFF_WH0RZ  1536     // [64][128]
#define OFF_WH0N   9728     // [64][64]
#define OFF_WX1RZ  13824    // [64][128]
#define OFF_WX1N   22016    // [64][64]
#define OFF_WH1RZ  26112    // [64][128]
#define OFF_WH1N   34304    // [64][64]
#define OFF_HS0    38400    // [2][64][32]
#define OFF_HS1    42496    // [2][64][32]
#define OFF_XS     46592    // [2][8][32]
#define OFF_OW     47104    // [64]
#define OFF_OB     47168    // [1]
#define SMEM_FLOATS 47172   // 188,688 bytes

__device__ __forceinline__ u64 pk2(float lo, float hi) {
    u64 r; asm("mov.b64 %0, {%1,%2};" : "=l"(r) : "f"(lo), "f"(hi)); return r;
}
__device__ __forceinline__ u64 dup2(float v) { return pk2(v, v); }
__device__ __forceinline__ float2 up2(u64 v) {
    float2 r; asm("mov.b64 {%0,%1}, %2;" : "=f"(r.x), "=f"(r.y) : "l"(v)); return r;
}
#define FFMA2(acc, a, b) \
    asm("fma.rn.f32x2 %0, %1, %2, %0;" : "+l"(acc) : "l"(a), "l"(b))

__device__ __forceinline__ float sigf(float x) {
    return 1.0f / (1.0f + __expf(-x));
}
__device__ __forceinline__ float tanhfast(float x) {
    float e = __expf(-2.0f * fabsf(x));
    float t = (1.0f - e) / (1.0f + e);
    return copysignf(t, x);
}

// Split-transpose W[192][K] (row-major) into:
//   rz[k*128 + ut*4 + gate*2 + lane]  (gates r,z)
//   n [k*64  + ut*2 + lane]           (gate n)
__device__ __forceinline__ void load_w_split(float* dstRZ, float* dstN,
                                             const float* __restrict__ src,
                                             int K, int tid) {
    for (int idx = tid; idx < G3 * K; idx += NT) {
        int g = idx / K;
        int k = idx - g * K;
        int gate = g >> 6;          // 0=r,1=z,2=n
        int j    = g & 63;
        int ut   = j >> 1;
        int lane = j & 1;
        float v = src[idx];
        if (gate < 2) dstRZ[k * 128 + ut * 4 + gate * 2 + lane] = v;
        else          dstN [k * 64  + ut * 2 + lane]            = v;
    }
}

// GRU cell for this thread's [2 units (packed f32x2) x 2 rows] tile.
// xsrc/hsrc k-major [k][ROWS]; weights in split rz/n layout.
template<int KIN>
__device__ __forceinline__ void gru_tile2(
    const float* __restrict__ Wxrz, const float* __restrict__ Wxn,
    const float* __restrict__ Whrz, const float* __restrict__ Whn,
    const float* __restrict__ xsrc, const float* __restrict__ hsrc,
    float* __restrict__ hdst,
    u64 br2, u64 bz2, u64 bi2, u64 bh2,
    int ut, int r0)
{
    u64 ar[2], az[2], ai[2], ah[2];
    ar[0] = br2; ar[1] = br2;
    az[0] = bz2; az[1] = bz2;
    ai[0] = bi2; ai[1] = bi2;
    ah[0] = bh2; ah[1] = bh2;

    const float* wxrz = Wxrz + ut * 4;
    const float* wxn  = Wxn  + ut * 2;
#pragma unroll
    for (int k = 0; k < KIN; k++) {
        float2 xv = *(const float2*)(xsrc + k * ROWS + r0);
        ulonglong2 wv = *(const ulonglong2*)(wxrz + k * 128);
        u64 wn = *(const u64*)(wxn + k * 64);
        u64 x0 = dup2(xv.x), x1 = dup2(xv.y);
        FFMA2(ar[0], wv.x, x0); FFMA2(ar[1], wv.x, x1);
        FFMA2(az[0], wv.y, x0); FFMA2(az[1], wv.y, x1);
        FFMA2(ai[0], wn,   x0); FFMA2(ai[1], wn,   x1);
    }

    const float* whrz = Whrz + ut * 4;
    const float* whn  = Whn  + ut * 2;
#pragma unroll 8
    for (int k = 0; k < Hh; k++) {
        float2 hv = *(const float2*)(hsrc + k * ROWS + r0);
        ulonglong2 wv = *(const ulonglong2*)(whrz + k * 128);
        u64 wn = *(const u64*)(whn + k * 64);
        u64 h0 = dup2(hv.x), h1 = dup2(hv.y);
        FFMA2(ar[0], wv.x, h0); FFMA2(ar[1], wv.x, h1);
        FFMA2(az[0], wv.y, h0); FFMA2(az[1], wv.y, h1);
        FFMA2(ah[0], wn,   h0); FFMA2(ah[1], wn,   h1);
    }

    // epilogue: r,z sigmoid; n = tanh(in + r*hn); h' = n + z*(h_old - n)
    const int j0 = ut * 2;
    float2 ho0 = *(const float2*)(hsrc + j0 * ROWS + r0);        // unit0, rows 0..1
    float2 ho1 = *(const float2*)(hsrc + (j0 + 1) * ROWS + r0);  // unit1
    float o0[2], o1[2];
    float hou0[2] = {ho0.x, ho0.y}, hou1[2] = {ho1.x, ho1.y};
#pragma unroll
    for (int rr = 0; rr < 2; rr++) {
        float2 arv = up2(ar[rr]), azv = up2(az[rr]);
        float2 aiv = up2(ai[rr]), ahv = up2(ah[rr]);
        {
            float r = sigf(arv.x), z = sigf(azv.x);
            float n = tanhfast(fmaf(r, ahv.x, aiv.x));
            o0[rr] = fmaf(z, hou0[rr] - n, n);
        }
        {
            float r = sigf(arv.y), z = sigf(azv.y);
            float n = tanhfast(fmaf(r, ahv.y, aiv.y));
            o1[rr] = fmaf(z, hou1[rr] - n, n);
        }
    }
    *(float2*)(hdst + j0 * ROWS + r0)       = make_float2(o0[0], o0[1]);
    *(float2*)(hdst + (j0 + 1) * ROWS + r0) = make_float2(o1[0], o1[1]);
}

extern __shared__ float sm[];

__global__ __launch_bounds__(NT, 1)
void gru_kernel(
    const float* __restrict__ x,
    const float* __restrict__ eWih0, const float* __restrict__ eWhh0,
    const float* __restrict__ ebih0, const float* __restrict__ ebhh0,
    const float* __restrict__ eWih1, const float* __restrict__ eWhh1,
    const float* __restrict__ ebih1, const float* __restrict__ ebhh1,
    const float* __restrict__ dWih0, const float* __restrict__ dWhh0,
    const float* __restrict__ dbih0, const float* __restrict__ dbhh0,
    const float* __restrict__ dWih1, const float* __restrict__ dWhh1,
    const float* __restrict__ dbih1, const float* __restrict__ dbhh1,
    const float* __restrict__ outW, const float* __restrict__ outb,
    float* __restrict__ out, int Bn, int TL)
{
    const int tid = threadIdx.x;
    const int b0  = blockIdx.x * ROWS;

    float* Wx0rz = sm + OFF_WX0RZ;  float* Wx0n = sm + OFF_WX0N;
    float* Wh0rz = sm + OFF_WH0RZ;  float* Wh0n = sm + OFF_WH0N;
    float* Wx1rz = sm + OFF_WX1RZ;  float* Wx1n = sm + OFF_WX1N;
    float* Wh1rz = sm + OFF_WH1RZ;  float* Wh1n = sm + OFF_WH1N;
    float* hs0 = sm + OFF_HS0;
    float* hs1 = sm + OFF_HS1;
    float* xs  = sm + OFF_XS;
    float* sOW = sm + OFF_OW;
    float* sOB = sm + OFF_OB;

    const int rt = tid & 15;         // row tile (2 rows)
    const int ut = tid >> 4;         // unit tile (2 units)
    const int r0 = rt * 2;
    const int j0 = ut * 2;

    // ---- stage encoder weights ----
    load_w_split(Wx0rz, Wx0n, eWih0, NINP, tid);
    load_w_split(Wh0rz, Wh0n, eWhh0, Hh, tid);
    load_w_split(Wx1rz, Wx1n, eWih1, Hh, tid);
    load_w_split(Wh1rz, Wh1n, eWhh1, Hh, tid);
    for (int i = tid; i < Hh * ROWS; i += NT) {
        hs0[i] = 0.0f; hs0[2048 + i] = 0.0f;
        hs1[i] = 0.0f; hs1[2048 + i] = 0.0f;
    }

    // ---- encoder bias pairs in registers ----
    u64 b0r, b0z, b0i, b0h, b1r, b1z, b1i, b1h;
    {
        float2 a, b;
        a = *(const float2*)(ebih0 + j0);        b = *(const float2*)(ebhh0 + j0);
        b0r = pk2(a.x + b.x, a.y + b.y);
        a = *(const float2*)(ebih0 + 64 + j0);   b = *(const float2*)(ebhh0 + 64 + j0);
        b0z = pk2(a.x + b.x, a.y + b.y);
        a = *(const float2*)(ebih0 + 128 + j0);  b0i = pk2(a.x, a.y);
        b = *(const float2*)(ebhh0 + 128 + j0);  b0h = pk2(b.x, b.y);
        a = *(const float2*)(ebih1 + j0);        b = *(const float2*)(ebhh1 + j0);
        b1r = pk2(a.x + b.x, a.y + b.y);
        a = *(const float2*)(ebih1 + 64 + j0);   b = *(const float2*)(ebhh1 + 64 + j0);
        b1z = pk2(a.x + b.x, a.y + b.y);
        a = *(const float2*)(ebih1 + 128 + j0);  b1i = pk2(a.x, a.y);
        b = *(const float2*)(ebhh1 + 128 + j0);  b1h = pk2(b.x, b.y);
    }

    // prestage x for t=0 into buffer 0
    const int xi = tid >> 5, xr = tid & 31;
    if (tid < NINP * ROWS) {
        float v = (b0 + xr < Bn)
            ? x[(size_t)(b0 + xr) * (TSEQ * NINP) + xi] : 0.0f;
        xs[xi * ROWS + xr] = v;
    }
    __syncthreads();

    // ---- encoder: 256 steps ----
    int cur = 0;
    for (int t = 0; t < TSEQ; t++) {
        float xreg = 0.0f;
        if (tid < NINP * ROWS && t + 1 < TSEQ && b0 + xr < Bn)
            xreg = x[(size_t)(b0 + xr) * (TSEQ * NINP) + (size_t)(t + 1) * NINP + xi];
        int nxt = cur ^ 1;
        gru_tile2<NINP>(Wx0rz, Wx0n, Wh0rz, Wh0n,
                        xs + cur * 256, hs0 + cur * 2048, hs0 + nxt * 2048,
                        b0r, b0z, b0i, b0h, ut, r0);
        if (tid < NINP * ROWS) xs[nxt * 256 + xi * ROWS + xr] = xreg;
        __syncthreads();
        gru_tile2<Hh>(Wx1rz, Wx1n, Wh1rz, Wh1n,
                      hs0 + nxt * 2048, hs1 + cur * 2048, hs1 + nxt * 2048,
                      b1r, b1z, b1i, b1h, ut, r0);
        cur = nxt;
        __syncthreads();
    }

    // ---- swap in decoder weights ----
    load_w_split(Wx0rz, Wx0n, dWih0, 1, tid);
    load_w_split(Wh0rz, Wh0n, dWhh0, Hh, tid);
    load_w_split(Wx1rz, Wx1n, dWih1, Hh, tid);
    load_w_split(Wh1rz, Wh1n, dWhh1, Hh, tid);
    if (tid < Hh) sOW[tid] = outW[tid];
    if (tid == 0) sOB[0] = outb[0];
    if (tid < ROWS) xs[tid] = 0.0f;      // prev cv = 0 (xs buffer 0, row-major k=0)
    {
        float2 a, b;
        a = *(const float2*)(dbih0 + j0);        b = *(const float2*)(dbhh0 + j0);
        b0r = pk2(a.x + b.x, a.y + b.y);
        a = *(const float2*)(dbih0 + 64 + j0);   b = *(const float2*)(dbhh0 + 64 + j0);
        b0z = pk2(a.x + b.x, a.y + b.y);
        a = *(const float2*)(dbih0 + 128 + j0);  b0i = pk2(a.x, a.y);
        b = *(const float2*)(dbhh0 + 128 + j0);  b0h = pk2(b.x, b.y);
        a = *(const float2*)(dbih1 + j0);        b = *(const float2*)(dbhh1 + j0);
        b1r = pk2(a.x + b.x, a.y + b.y);
        a = *(const float2*)(dbih1 + 64 + j0);   b = *(const float2*)(dbhh1 + 64 + j0);
        b1z = pk2(a.x + b.x, a.y + b.y);
        a = *(const float2*)(dbih1 + 128 + j0);  b1i = pk2(a.x, a.y);
        b = *(const float2*)(dbhh1 + 128 + j0);  b1h = pk2(b.x, b.y);
    }
    __syncthreads();

    // ---- decoder: TL autoregressive steps ----
    for (int s = 0; s < TL; s++) {
        int nxt = cur ^ 1;
        gru_tile2<1>(Wx0rz, Wx0n, Wh0rz, Wh0n,
                     xs, hs0 + cur * 2048, hs0 + nxt * 2048,
                     b0r, b0z, b0i, b0h, ut, r0);
        __syncthreads();
        gru_tile2<Hh>(Wx1rz, Wx1n, Wh1rz, Wh1n,
                      hs0 + nxt * 2048, hs1 + cur * 2048, hs1 + nxt * 2048,
                      b1r, b1z, b1i, b1h, ut, r0);
        __syncthreads();
        if (tid < ROWS) {
            float acc = sOB[0];
            const float* hp = hs1 + nxt * 2048 + tid;
            #pragma unroll 8
            for (int j = 0; j < Hh; j++)
                acc = fmaf(sOW[j], hp[j * ROWS], acc);
            if (b0 + tid < Bn)
                out[(size_t)(b0 + tid) * TL + s] = acc;
            xs[tid] = acc;
        }
        cur = nxt;
        __syncthreads();
    }
}

extern "C" void kernel_launch(void* const* d_in, const int* in_sizes, int n_in,
                              void* d_out, int out_size) {
    const float* x      = (const float*)d_in[0];
    const float* eWih0  = (const float*)d_in[1];
    const float* eWhh0  = (const float*)d_in[2];
    const float* ebih0  = (const float*)d_in[3];
    const float* ebhh0  = (const float*)d_in[4];
    const float* eWih1  = (const float*)d_in[5];
    const float* eWhh1  = (const float*)d_in[6];
    const float* ebih1  = (const float*)d_in[7];
    const float* ebhh1  = (const float*)d_in[8];
    const float* dWih0  = (const float*)d_in[9];
    const float* dWhh0  = (const float*)d_in[10];
    const float* dbih0  = (const float*)d_in[11];
    const float* dbhh0  = (const float*)d_in[12];
    const float* dWih1  = (const float*)d_in[13];
    const float* dWhh1  = (const float*)d_in[14];
    const float* dbih1  = (const float*)d_in[15];
    const float* dbhh1  = (const float*)d_in[16];
    const float* outW   = (const float*)d_in[17];
    const float* outb   = (const float*)d_in[18];

    int B  = in_sizes[0] / (TSEQ * NINP);
    int TL = out_size / B;                       // 180
    int grid = (B + ROWS - 1) / ROWS;            // 128
    size_t smem = SMEM_FLOATS * sizeof(float);   // ~188 KB

    cudaFuncSetAttribute(gru_kernel,
                         cudaFuncAttributeMaxDynamicSharedMemorySize,
                         (int)smem);

    gru_kernel<<<grid, NT, smem>>>(
        x, eWih0, eWhh0, ebih0, ebhh0, eWih1, eWhh1, ebih1, ebhh1,
        dWih0, dWhh0, dbih0, dbhh0, dWih1, dWhh1, dbih1, dbhh1,
        outW, outb, (float*)d_out, B, TL);
}